// round 1
// baseline (speedup 1.0000x reference)
#include <cuda_runtime.h>
#include <math.h>

#define BB 2
#define TT 4096
#define EE 512
#define HH 8
#define DD 64
#define CHUNK 128
#define NCH (TT/CHUNK)     // 32
#define NBH (BB*HH)        // 16
#define EPSF 1e-6f

#define MROWS (BB*TT)      // 8192

// ---------------- scratch (__device__ globals; no allocation allowed) ----------
__device__ float g_q[MROWS*EE];
__device__ float g_k[MROWS*EE];
__device__ float g_v[MROWS*EE];
__device__ float g_attn[MROWS*EE];
__device__ float g_Mc[NBH*NCH*DD*DD];
__device__ float g_zc[NBH*NCH*DD];
__device__ float g_Mp[NBH*NCH*DD*DD];
__device__ float g_zp[NBH*NCH*DD];

// ---------------- GEMM: Y[m][n] = sum_k A[m][k]*W[n][k] + bias[n], opt elu+1 ---
// M=8192, N=512, K=512. BM=BN=128, BK=16, 256 threads, 8x8 register tile.
template<int ACT>
__global__ __launch_bounds__(256) void gemm_kernel(
    const float* __restrict__ A, const float* __restrict__ W,
    const float* __restrict__ bias, float* __restrict__ Y)
{
    const int K = EE, N = EE;
    __shared__ __align__(16) float As[16][132];
    __shared__ __align__(16) float Ws[16][132];

    int m0 = blockIdx.x * 128;
    int n0 = blockIdx.y * 128;
    int tid = threadIdx.x;
    int tx = tid & 15, ty = tid >> 4;

    float acc[8][8];
#pragma unroll
    for (int i = 0; i < 8; i++)
#pragma unroll
        for (int j = 0; j < 8; j++) acc[i][j] = 0.f;

    for (int k0 = 0; k0 < K; k0 += 16) {
        // load tiles (transposed into smem): 512 float4 each for A and W
#pragma unroll
        for (int p = 0; p < 2; p++) {
            int idx = tid + p * 256;         // 0..511
            int row = idx >> 2;              // 0..127
            int c4  = (idx & 3) * 4;         // 0,4,8,12
            float4 a = *(const float4*)&A[(size_t)(m0 + row) * K + k0 + c4];
            As[c4 + 0][row] = a.x; As[c4 + 1][row] = a.y;
            As[c4 + 2][row] = a.z; As[c4 + 3][row] = a.w;
            float4 w = *(const float4*)&W[(size_t)(n0 + row) * K + k0 + c4];
            Ws[c4 + 0][row] = w.x; Ws[c4 + 1][row] = w.y;
            Ws[c4 + 2][row] = w.z; Ws[c4 + 3][row] = w.w;
        }
        __syncthreads();

#pragma unroll
        for (int kk = 0; kk < 16; kk++) {
            float4 a0 = *(const float4*)&As[kk][ty * 8];
            float4 a1 = *(const float4*)&As[kk][ty * 8 + 4];
            float4 b0 = *(const float4*)&Ws[kk][tx * 8];
            float4 b1 = *(const float4*)&Ws[kk][tx * 8 + 4];
            float ra[8] = {a0.x, a0.y, a0.z, a0.w, a1.x, a1.y, a1.z, a1.w};
            float rb[8] = {b0.x, b0.y, b0.z, b0.w, b1.x, b1.y, b1.z, b1.w};
#pragma unroll
            for (int i = 0; i < 8; i++)
#pragma unroll
                for (int j = 0; j < 8; j++) acc[i][j] += ra[i] * rb[j];
        }
        __syncthreads();
    }

#pragma unroll
    for (int i = 0; i < 8; i++) {
        int m = m0 + ty * 8 + i;
#pragma unroll
        for (int j = 0; j < 8; j++) {
            int n = n0 + tx * 8 + j;
            float yv = acc[i][j] + bias[n];
            if (ACT) yv = (yv > 0.f) ? (yv + 1.f) : expf(yv);
            Y[(size_t)m * N + n] = yv;
        }
    }
}

// ---------------- Pass A: per-chunk KV outer sums + key sums -------------------
__global__ __launch_bounds__(256) void chunk_sums_kernel()
{
    int blk = blockIdx.x;           // bh*NCH + c
    int bh = blk / NCH, c = blk % NCH;
    int b = bh / HH, h = bh % HH;

    extern __shared__ float sm[];
    float* sk = sm;                 // [128][65]
    float* sv = sm + CHUNK * 65;    // [128][65]

    int tid = threadIdx.x;
    const float* kg = g_k + ((size_t)b * TT + (size_t)c * CHUNK) * EE + h * DD;
    const float* vg = g_v + ((size_t)b * TT + (size_t)c * CHUNK) * EE + h * DD;

    for (int i = tid; i < CHUNK * 16; i += 256) {
        int t = i >> 4, d4 = (i & 15) * 4;
        float4 a = *(const float4*)&kg[(size_t)t * EE + d4];
        sk[t * 65 + d4 + 0] = a.x; sk[t * 65 + d4 + 1] = a.y;
        sk[t * 65 + d4 + 2] = a.z; sk[t * 65 + d4 + 3] = a.w;
        float4 w = *(const float4*)&vg[(size_t)t * EE + d4];
        sv[t * 65 + d4 + 0] = w.x; sv[t * 65 + d4 + 1] = w.y;
        sv[t * 65 + d4 + 2] = w.z; sv[t * 65 + d4 + 3] = w.w;
    }
    __syncthreads();

    int d = tid >> 2;
    int eg = (tid & 3) * 16;
    float acc[16];
#pragma unroll
    for (int j = 0; j < 16; j++) acc[j] = 0.f;
    float zacc = 0.f;

    for (int t = 0; t < CHUNK; t++) {
        float kv = sk[t * 65 + d];
        zacc += kv;
        const float* vr = &sv[t * 65 + eg];
#pragma unroll
        for (int j = 0; j < 16; j++) acc[j] += kv * vr[j];
    }

    float* Mout = g_Mc + (size_t)blk * DD * DD + d * DD + eg;
#pragma unroll
    for (int j = 0; j < 16; j++) Mout[j] = acc[j];
    if ((tid & 3) == 0) g_zc[(size_t)blk * DD + d] = zacc;
}

// ---------------- Pass B: exclusive prefix over chunks -------------------------
__global__ void prefix_kernel()
{
    int idx = blockIdx.x * 256 + threadIdx.x;
    const int PER = DD * DD + DD;   // 4160
    if (idx >= NBH * PER) return;
    int bh = idx / PER;
    int r  = idx % PER;
    if (r < DD * DD) {
        float run = 0.f;
        for (int c = 0; c < NCH; c++) {
            size_t o = (size_t)(bh * NCH + c) * DD * DD + r;
            g_Mp[o] = run;
            run += g_Mc[o];
        }
    } else {
        int d = r - DD * DD;
        float run = 0.f;
        for (int c = 0; c < NCH; c++) {
            size_t o = (size_t)(bh * NCH + c) * DD + d;
            g_zp[o] = run;
            run += g_zc[o];
        }
    }
}

// ---------------- Pass C: per-chunk output ------------------------------------
__global__ __launch_bounds__(256) void chunk_attn_kernel()
{
    int blk = blockIdx.x;
    int bh = blk / NCH, c = blk % NCH;
    int b = bh / HH, h = bh % HH;

    extern __shared__ float sm[];
    float* sq  = sm;                        // [128][65]
    float* sk  = sq + 128 * 65;             // [128][65]
    float* sv  = sk + 128 * 65;             // [128][65]
    float* sS  = sv + 128 * 65;             // [64][65]
    float* sz  = sS + 64 * 65;              // [64]
    float* sdi = sz + 64;                   // [128]
    float* sA  = sdi + 128;                 // [128][128]

    int tid = threadIdx.x;
    const float* qg = g_q + ((size_t)b * TT + (size_t)c * CHUNK) * EE + h * DD;
    const float* kg = g_k + ((size_t)b * TT + (size_t)c * CHUNK) * EE + h * DD;
    const float* vg = g_v + ((size_t)b * TT + (size_t)c * CHUNK) * EE + h * DD;
    const float* Mp = g_Mp + (size_t)blk * DD * DD;
    const float* zp = g_zp + (size_t)blk * DD;

    for (int i = tid; i < CHUNK * 16; i += 256) {
        int t = i >> 4, d4 = (i & 15) * 4;
        float4 a = *(const float4*)&qg[(size_t)t * EE + d4];
        sq[t * 65 + d4 + 0] = a.x; sq[t * 65 + d4 + 1] = a.y;
        sq[t * 65 + d4 + 2] = a.z; sq[t * 65 + d4 + 3] = a.w;
        float4 w = *(const float4*)&kg[(size_t)t * EE + d4];
        sk[t * 65 + d4 + 0] = w.x; sk[t * 65 + d4 + 1] = w.y;
        sk[t * 65 + d4 + 2] = w.z; sk[t * 65 + d4 + 3] = w.w;
        float4 v = *(const float4*)&vg[(size_t)t * EE + d4];
        sv[t * 65 + d4 + 0] = v.x; sv[t * 65 + d4 + 1] = v.y;
        sv[t * 65 + d4 + 2] = v.z; sv[t * 65 + d4 + 3] = v.w;
    }
    for (int i = tid; i < DD * DD; i += 256) {
        sS[(i >> 6) * 65 + (i & 63)] = Mp[i];
    }
    if (tid < DD) sz[tid] = zp[tid];
    __syncthreads();

    // A[t][s] = q_t . k_s  (s <= t)
    for (int i = tid; i < 128 * 128; i += 256) {
        int t = i >> 7, s = i & 127;
        if (s <= t) {
            const float* qr = &sq[t * 65];
            const float* kr = &sk[s * 65];
            float a = 0.f;
#pragma unroll
            for (int dd = 0; dd < DD; dd++) a += qr[dd] * kr[dd];
            sA[t * 128 + s] = a;
        }
    }
    __syncthreads();

    // denominators
    if (tid < 128) {
        int t = tid;
        const float* qr = &sq[t * 65];
        float den = EPSF;
#pragma unroll
        for (int dd = 0; dd < DD; dd++) den += qr[dd] * sz[dd];
        for (int s = 0; s <= t; s++) den += sA[t * 128 + s];
        sdi[t] = 1.f / den;
    }
    __syncthreads();

    // out[t][e] = ( q_t . S_pref[:,e] + sum_{s<=t} A[t][s] v_s[e] ) * inv_den[t]
    float* og = g_attn + ((size_t)b * TT + (size_t)c * CHUNK) * EE + h * DD;
    for (int i = tid; i < 128 * 64; i += 256) {
        int t = i >> 6, e = i & 63;
        const float* qr = &sq[t * 65];
        float acc = 0.f;
#pragma unroll
        for (int dd = 0; dd < DD; dd++) acc += qr[dd] * sS[dd * 65 + e];
        const float* ar = &sA[t * 128];
        for (int s = 0; s <= t; s++) acc += ar[s] * sv[s * 65 + e];
        og[(size_t)t * EE + e] = acc * sdi[t];
    }
}

// ---------------- host ----------------------------------------------------------
extern "C" void kernel_launch(void* const* d_in, const int* in_sizes, int n_in,
                              void* d_out, int out_size)
{
    const float* x  = (const float*)d_in[0];
    const float* Wq = (const float*)d_in[1];
    const float* bq = (const float*)d_in[2];
    const float* Wk = (const float*)d_in[3];
    const float* bk = (const float*)d_in[4];
    const float* Wv = (const float*)d_in[5];
    const float* bv = (const float*)d_in[6];
    const float* Wo = (const float*)d_in[7];
    const float* bo = (const float*)d_in[8];
    float* out = (float*)d_out;

    float *pq, *pk, *pv, *pa;
    cudaGetSymbolAddress((void**)&pq, g_q);
    cudaGetSymbolAddress((void**)&pk, g_k);
    cudaGetSymbolAddress((void**)&pv, g_v);
    cudaGetSymbolAddress((void**)&pa, g_attn);

    // set max dynamic smem (idempotent, non-capturing host calls)
    cudaFuncSetAttribute(chunk_sums_kernel,
                         cudaFuncAttributeMaxDynamicSharedMemorySize, 2 * 128 * 65 * 4);
    int smC = (3 * 128 * 65 + 64 * 65 + 64 + 128 + 128 * 128) * 4;
    cudaFuncSetAttribute(chunk_attn_kernel,
                         cudaFuncAttributeMaxDynamicSharedMemorySize, smC);

    dim3 ggrid(MROWS / 128, EE / 128);   // 64 x 4

    gemm_kernel<1><<<ggrid, 256>>>(x, Wq, bq, pq);
    gemm_kernel<1><<<ggrid, 256>>>(x, Wk, bk, pk);
    gemm_kernel<0><<<ggrid, 256>>>(x, Wv, bv, pv);

    chunk_sums_kernel<<<NBH * NCH, 256, 2 * 128 * 65 * 4>>>();

    int totalPref = NBH * (DD * DD + DD);
    prefix_kernel<<<(totalPref + 255) / 256, 256>>>();

    chunk_attn_kernel<<<NBH * NCH, 256, smC>>>();

    gemm_kernel<0><<<ggrid, 256>>>(pa, Wo, bo, out);
}

// round 2
// speedup vs baseline: 1.0001x; 1.0001x over previous
#include <cuda_runtime.h>
#include <math.h>

#define BB 2
#define TT 4096
#define EE 512
#define HH 8
#define DD 64
#define CHUNK 128
#define NCH (TT/CHUNK)     // 32
#define NBH (BB*HH)        // 16
#define EPSF 1e-6f

#define MROWS (BB*TT)      // 8192

// ---------------- scratch (__device__ globals; no allocation allowed) ----------
__device__ float g_q[MROWS*EE];
__device__ float g_k[MROWS*EE];
__device__ float g_v[MROWS*EE];
__device__ float g_attn[MROWS*EE];
__device__ float g_Mc[NBH*NCH*DD*DD];
__device__ float g_zc[NBH*NCH*DD];
__device__ float g_Mp[NBH*NCH*DD*DD];
__device__ float g_zp[NBH*NCH*DD];

// ---------------- GEMM: Y[m][n] = sum_k A[m][k]*W[n][k] + bias[n], opt elu+1 ---
// M=8192, N=512, K=512. BM=BN=128, BK=16, 256 threads, 8x8 register tile.
template<int ACT>
__global__ __launch_bounds__(256) void gemm_kernel(
    const float* __restrict__ A, const float* __restrict__ W,
    const float* __restrict__ bias, float* __restrict__ Y)
{
    const int K = EE, N = EE;
    __shared__ __align__(16) float As[16][132];
    __shared__ __align__(16) float Ws[16][132];

    int m0 = blockIdx.x * 128;
    int n0 = blockIdx.y * 128;
    int tid = threadIdx.x;
    int tx = tid & 15, ty = tid >> 4;

    float acc[8][8];
#pragma unroll
    for (int i = 0; i < 8; i++)
#pragma unroll
        for (int j = 0; j < 8; j++) acc[i][j] = 0.f;

    for (int k0 = 0; k0 < K; k0 += 16) {
        // load tiles (transposed into smem): 512 float4 each for A and W
#pragma unroll
        for (int p = 0; p < 2; p++) {
            int idx = tid + p * 256;         // 0..511
            int row = idx >> 2;              // 0..127
            int c4  = (idx & 3) * 4;         // 0,4,8,12
            float4 a = *(const float4*)&A[(size_t)(m0 + row) * K + k0 + c4];
            As[c4 + 0][row] = a.x; As[c4 + 1][row] = a.y;
            As[c4 + 2][row] = a.z; As[c4 + 3][row] = a.w;
            float4 w = *(const float4*)&W[(size_t)(n0 + row) * K + k0 + c4];
            Ws[c4 + 0][row] = w.x; Ws[c4 + 1][row] = w.y;
            Ws[c4 + 2][row] = w.z; Ws[c4 + 3][row] = w.w;
        }
        __syncthreads();

#pragma unroll
        for (int kk = 0; kk < 16; kk++) {
            float4 a0 = *(const float4*)&As[kk][ty * 8];
            float4 a1 = *(const float4*)&As[kk][ty * 8 + 4];
            float4 b0 = *(const float4*)&Ws[kk][tx * 8];
            float4 b1 = *(const float4*)&Ws[kk][tx * 8 + 4];
            float ra[8] = {a0.x, a0.y, a0.z, a0.w, a1.x, a1.y, a1.z, a1.w};
            float rb[8] = {b0.x, b0.y, b0.z, b0.w, b1.x, b1.y, b1.z, b1.w};
#pragma unroll
            for (int i = 0; i < 8; i++)
#pragma unroll
                for (int j = 0; j < 8; j++) acc[i][j] += ra[i] * rb[j];
        }
        __syncthreads();
    }

#pragma unroll
    for (int i = 0; i < 8; i++) {
        int m = m0 + ty * 8 + i;
#pragma unroll
        for (int j = 0; j < 8; j++) {
            int n = n0 + tx * 8 + j;
            float yv = acc[i][j] + bias[n];
            if (ACT) yv = (yv > 0.f) ? (yv + 1.f) : expf(yv);
            Y[(size_t)m * N + n] = yv;
        }
    }
}

// ---------------- Pass A: per-chunk KV outer sums + key sums -------------------
__global__ __launch_bounds__(256) void chunk_sums_kernel()
{
    int blk = blockIdx.x;           // bh*NCH + c
    int bh = blk / NCH, c = blk % NCH;
    int b = bh / HH, h = bh % HH;

    extern __shared__ float sm[];
    float* sk = sm;                 // [128][65]
    float* sv = sm + CHUNK * 65;    // [128][65]

    int tid = threadIdx.x;
    const float* kg = g_k + ((size_t)b * TT + (size_t)c * CHUNK) * EE + h * DD;
    const float* vg = g_v + ((size_t)b * TT + (size_t)c * CHUNK) * EE + h * DD;

    for (int i = tid; i < CHUNK * 16; i += 256) {
        int t = i >> 4, d4 = (i & 15) * 4;
        float4 a = *(const float4*)&kg[(size_t)t * EE + d4];
        sk[t * 65 + d4 + 0] = a.x; sk[t * 65 + d4 + 1] = a.y;
        sk[t * 65 + d4 + 2] = a.z; sk[t * 65 + d4 + 3] = a.w;
        float4 w = *(const float4*)&vg[(size_t)t * EE + d4];
        sv[t * 65 + d4 + 0] = w.x; sv[t * 65 + d4 + 1] = w.y;
        sv[t * 65 + d4 + 2] = w.z; sv[t * 65 + d4 + 3] = w.w;
    }
    __syncthreads();

    int d = tid >> 2;
    int eg = (tid & 3) * 16;
    float acc[16];
#pragma unroll
    for (int j = 0; j < 16; j++) acc[j] = 0.f;
    float zacc = 0.f;

    for (int t = 0; t < CHUNK; t++) {
        float kv = sk[t * 65 + d];
        zacc += kv;
        const float* vr = &sv[t * 65 + eg];
#pragma unroll
        for (int j = 0; j < 16; j++) acc[j] += kv * vr[j];
    }

    float* Mout = g_Mc + (size_t)blk * DD * DD + d * DD + eg;
#pragma unroll
    for (int j = 0; j < 16; j++) Mout[j] = acc[j];
    if ((tid & 3) == 0) g_zc[(size_t)blk * DD + d] = zacc;
}

// ---------------- Pass B: exclusive prefix over chunks -------------------------
__global__ void prefix_kernel()
{
    int idx = blockIdx.x * 256 + threadIdx.x;
    const int PER = DD * DD + DD;   // 4160
    if (idx >= NBH * PER) return;
    int bh = idx / PER;
    int r  = idx % PER;
    if (r < DD * DD) {
        float run = 0.f;
        for (int c = 0; c < NCH; c++) {
            size_t o = (size_t)(bh * NCH + c) * DD * DD + r;
            g_Mp[o] = run;
            run += g_Mc[o];
        }
    } else {
        int d = r - DD * DD;
        float run = 0.f;
        for (int c = 0; c < NCH; c++) {
            size_t o = (size_t)(bh * NCH + c) * DD + d;
            g_zp[o] = run;
            run += g_zc[o];
        }
    }
}

// ---------------- Pass C: per-chunk output ------------------------------------
__global__ __launch_bounds__(256) void chunk_attn_kernel()
{
    int blk = blockIdx.x;
    int bh = blk / NCH, c = blk % NCH;
    int b = bh / HH, h = bh % HH;

    extern __shared__ float sm[];
    float* sq  = sm;                        // [128][65]
    float* sk  = sq + 128 * 65;             // [128][65]
    float* sv  = sk + 128 * 65;             // [128][65]
    float* sS  = sv + 128 * 65;             // [64][65]
    float* sz  = sS + 64 * 65;              // [64]
    float* sdi = sz + 64;                   // [128]
    float* sA  = sdi + 128;                 // [128][128]

    int tid = threadIdx.x;
    const float* qg = g_q + ((size_t)b * TT + (size_t)c * CHUNK) * EE + h * DD;
    const float* kg = g_k + ((size_t)b * TT + (size_t)c * CHUNK) * EE + h * DD;
    const float* vg = g_v + ((size_t)b * TT + (size_t)c * CHUNK) * EE + h * DD;
    const float* Mp = g_Mp + (size_t)blk * DD * DD;
    const float* zp = g_zp + (size_t)blk * DD;

    for (int i = tid; i < CHUNK * 16; i += 256) {
        int t = i >> 4, d4 = (i & 15) * 4;
        float4 a = *(const float4*)&qg[(size_t)t * EE + d4];
        sq[t * 65 + d4 + 0] = a.x; sq[t * 65 + d4 + 1] = a.y;
        sq[t * 65 + d4 + 2] = a.z; sq[t * 65 + d4 + 3] = a.w;
        float4 w = *(const float4*)&kg[(size_t)t * EE + d4];
        sk[t * 65 + d4 + 0] = w.x; sk[t * 65 + d4 + 1] = w.y;
        sk[t * 65 + d4 + 2] = w.z; sk[t * 65 + d4 + 3] = w.w;
        float4 v = *(const float4*)&vg[(size_t)t * EE + d4];
        sv[t * 65 + d4 + 0] = v.x; sv[t * 65 + d4 + 1] = v.y;
        sv[t * 65 + d4 + 2] = v.z; sv[t * 65 + d4 + 3] = v.w;
    }
    for (int i = tid; i < DD * DD; i += 256) {
        sS[(i >> 6) * 65 + (i & 63)] = Mp[i];
    }
    if (tid < DD) sz[tid] = zp[tid];
    __syncthreads();

    // A[t][s] = q_t . k_s  (s <= t)
    for (int i = tid; i < 128 * 128; i += 256) {
        int t = i >> 7, s = i & 127;
        if (s <= t) {
            const float* qr = &sq[t * 65];
            const float* kr = &sk[s * 65];
            float a = 0.f;
#pragma unroll
            for (int dd = 0; dd < DD; dd++) a += qr[dd] * kr[dd];
            sA[t * 128 + s] = a;
        }
    }
    __syncthreads();

    // denominators
    if (tid < 128) {
        int t = tid;
        const float* qr = &sq[t * 65];
        float den = EPSF;
#pragma unroll
        for (int dd = 0; dd < DD; dd++) den += qr[dd] * sz[dd];
        for (int s = 0; s <= t; s++) den += sA[t * 128 + s];
        sdi[t] = 1.f / den;
    }
    __syncthreads();

    // out[t][e] = ( q_t . S_pref[:,e] + sum_{s<=t} A[t][s] v_s[e] ) * inv_den[t]
    float* og = g_attn + ((size_t)b * TT + (size_t)c * CHUNK) * EE + h * DD;
    for (int i = tid; i < 128 * 64; i += 256) {
        int t = i >> 6, e = i & 63;
        const float* qr = &sq[t * 65];
        float acc = 0.f;
#pragma unroll
        for (int dd = 0; dd < DD; dd++) acc += qr[dd] * sS[dd * 65 + e];
        const float* ar = &sA[t * 128];
        for (int s = 0; s <= t; s++) acc += ar[s] * sv[s * 65 + e];
        og[(size_t)t * EE + e] = acc * sdi[t];
    }
}

// ---------------- host ----------------------------------------------------------
extern "C" void kernel_launch(void* const* d_in, const int* in_sizes, int n_in,
                              void* d_out, int out_size)
{
    const float* x  = (const float*)d_in[0];
    const float* Wq = (const float*)d_in[1];
    const float* bq = (const float*)d_in[2];
    const float* Wk = (const float*)d_in[3];
    const float* bk = (const float*)d_in[4];
    const float* Wv = (const float*)d_in[5];
    const float* bv = (const float*)d_in[6];
    const float* Wo = (const float*)d_in[7];
    const float* bo = (const float*)d_in[8];
    float* out = (float*)d_out;

    float *pq, *pk, *pv, *pa;
    cudaGetSymbolAddress((void**)&pq, g_q);
    cudaGetSymbolAddress((void**)&pk, g_k);
    cudaGetSymbolAddress((void**)&pv, g_v);
    cudaGetSymbolAddress((void**)&pa, g_attn);

    // set max dynamic smem (idempotent, non-capturing host calls)
    cudaFuncSetAttribute(chunk_sums_kernel,
                         cudaFuncAttributeMaxDynamicSharedMemorySize, 2 * 128 * 65 * 4);
    int smC = (3 * 128 * 65 + 64 * 65 + 64 + 128 + 128 * 128) * 4;
    cudaFuncSetAttribute(chunk_attn_kernel,
                         cudaFuncAttributeMaxDynamicSharedMemorySize, smC);

    dim3 ggrid(MROWS / 128, EE / 128);   // 64 x 4

    gemm_kernel<1><<<ggrid, 256>>>(x, Wq, bq, pq);
    gemm_kernel<1><<<ggrid, 256>>>(x, Wk, bk, pk);
    gemm_kernel<0><<<ggrid, 256>>>(x, Wv, bv, pv);

    chunk_sums_kernel<<<NBH * NCH, 256, 2 * 128 * 65 * 4>>>();

    int totalPref = NBH * (DD * DD + DD);
    prefix_kernel<<<(totalPref + 255) / 256, 256>>>();

    chunk_attn_kernel<<<NBH * NCH, 256, smC>>>();

    gemm_kernel<0><<<ggrid, 256>>>(pa, Wo, bo, out);
}